// round 16
// baseline (speedup 1.0000x reference)
#include <cuda_runtime.h>
#include <cuda_fp16.h>
#include <math.h>
#include <stdint.h>

// Problem constants
#define BATCH 16
#define C 384
#define HH 56
#define WW 56
#define HW (HH*WW)            // 3136
#define NTOK (BATCH*HW)       // 50176
#define HEADS 12
#define DHEAD 32
#define WS 14
#define NWIN_SIDE 4
#define WIN_PER_B 16
#define NWIN (BATCH*WIN_PER_B) // 256
#define NTOKW (WS*WS)          // 196
#define MLP_HID (4*C)          // 1536
#define QKV_DIM (3*C)          // 1152

// ---------------- scratch buffers -------------------------------------------
__device__ __half g_x1[(size_t)NTOK * C];        // residual stream (half)
__device__ __half g_x2[(size_t)NTOK * C];
__device__ __half g_xn[(size_t)NTOK * C];        // LN out (half)
__device__ __half g_qkv[(size_t)NTOK * QKV_DIM];
__device__ __half g_attn[(size_t)NTOK * C];
__device__ __half g_h[(size_t)NTOK * MLP_HID];
// half weight copies
__device__ __half g_wq[(size_t)QKV_DIM * C];
__device__ __half g_wp[(size_t)C * C];
__device__ __half g_w1[(size_t)MLP_HID * C];
__device__ __half g_w2[(size_t)C * MLP_HID];

__device__ __forceinline__ uint32_t pack_h2(float a, float b) {
    __half2 h = __floats2half2_rn(a, b);
    return *reinterpret_cast<uint32_t*>(&h);
}

#define MMA_F16_K16(d, a, b)                                           \
    asm volatile(                                                      \
        "mma.sync.aligned.m16n8k16.row.col.f32.f16.f16.f32 "           \
        "{%0,%1,%2,%3},{%4,%5,%6,%7},{%8,%9},{%0,%1,%2,%3};\n"         \
        : "+f"(d[0]), "+f"(d[1]), "+f"(d[2]), "+f"(d[3])               \
        : "r"(a[0]), "r"(a[1]), "r"(a[2]), "r"(a[3]), "r"(b[0]), "r"(b[1]))

#define MMA_F16_K8(d, a, b0)                                           \
    asm volatile(                                                      \
        "mma.sync.aligned.m16n8k8.row.col.f32.f16.f16.f32 "            \
        "{%0,%1,%2,%3},{%4,%5},{%6},{%0,%1,%2,%3};\n"                  \
        : "+f"(d[0]), "+f"(d[1]), "+f"(d[2]), "+f"(d[3])               \
        : "r"(a[0]), "r"(a[1]), "r"(b0))

#define LDMATRIX_X4(r0, r1, r2, r3, addr)                              \
    asm volatile("ldmatrix.sync.aligned.m8n8.x4.shared.b16 "           \
                 "{%0,%1,%2,%3}, [%4];"                                \
                 : "=r"(r0), "=r"(r1), "=r"(r2), "=r"(r3) : "r"(addr))

__device__ __forceinline__ void cpasync16(void* smem_dst, const void* gsrc) {
    uint32_t s = (uint32_t)__cvta_generic_to_shared(smem_dst);
    asm volatile("cp.async.cg.shared.global [%0], [%1], 16;" :: "r"(s), "l"(gsrc));
}

// ---------------- weight conversion fp32 -> fp16 -----------------------------
#define SQ (QKV_DIM*C)
#define SP (C*C)
#define S1 (MLP_HID*C)
#define S2 (C*MLP_HID)
__global__ void cvt_weights_kernel(const float* __restrict__ wq, const float* __restrict__ wp,
                                   const float* __restrict__ w1, const float* __restrict__ w2,
                                   __half* oq, __half* op_, __half* o1, __half* o2)
{
    int i = blockIdx.x * 256 + threadIdx.x;
    if (i < SQ) oq[i] = __float2half(wq[i]);
    else if (i < SQ + SP) op_[i - SQ] = __float2half(wp[i - SQ]);
    else if (i < SQ + SP + S1) o1[i - SQ - SP] = __float2half(w1[i - SQ - SP]);
    else if (i < SQ + SP + S1 + S2) o2[i - SQ - SP - S1] = __float2half(w2[i - SQ - SP - S1]);
}

// ---------------- depthwise conv + bias + residual, NCHW -> BHWC (half out) --
__global__ void conv_pe_kernel(const float* __restrict__ x,
                               const float* __restrict__ cw,
                               const float* __restrict__ cb,
                               __half* __restrict__ out)
{
    __shared__ float sx[3][58][33];
    int c0 = blockIdx.x * 32;
    int h  = blockIdx.y;
    int b  = blockIdx.z;
    int tid = threadIdx.x;

    for (int idx = tid; idx < 32 * 3 * 58; idx += 256) {
        int wq = idx % 58;
        int t  = idx / 58;
        int hh = t % 3;
        int c  = t / 3;
        int gh = h + hh - 1, gw = wq - 1;
        float v = 0.f;
        if (gh >= 0 && gh < HH && gw >= 0 && gw < WW)
            v = x[(size_t)(b * C + c0 + c) * HW + gh * WW + gw];
        sx[hh][wq][c] = v;
    }
    __syncthreads();

    // 2 channels per thread, half2 stores
    for (int o = tid; o < 16 * WW; o += 256) {
        int cp = (o & 15) * 2, w = o >> 4;
        float s0 = cb[c0 + cp]     + sx[1][w + 1][cp];
        float s1 = cb[c0 + cp + 1] + sx[1][w + 1][cp + 1];
        const float* wt0 = cw + (size_t)(c0 + cp) * 9;
        const float* wt1 = wt0 + 9;
        #pragma unroll
        for (int dy = 0; dy < 3; dy++)
            #pragma unroll
            for (int dx = 0; dx < 3; dx++) {
                s0 += sx[dy][w + dx][cp]     * wt0[dy * 3 + dx];
                s1 += sx[dy][w + dx][cp + 1] * wt1[dy * 3 + dx];
            }
        *(__half2*)(out + (size_t)(b * HW + h * WW + w) * C + c0 + cp) =
            __floats2half2_rn(s0, s1);
    }
}

// ---------------- layer norm over C=384, half in / half out ------------------
__global__ void ln_kernel(const __half* __restrict__ x,
                          const float* __restrict__ w,
                          const float* __restrict__ b,
                          __half* __restrict__ y)
{
    __shared__ float red[4];
    int t = blockIdx.x;
    int tid = threadIdx.x;
    const __half* xr = x + (size_t)t * C;

    float v0 = __half2float(xr[tid]);
    float v1 = __half2float(xr[tid + 128]);
    float v2 = __half2float(xr[tid + 256]);

    float s = v0 + v1 + v2;
    for (int o = 16; o > 0; o >>= 1) s += __shfl_down_sync(0xffffffffu, s, o);
    if ((tid & 31) == 0) red[tid >> 5] = s;
    __syncthreads();
    float tot = red[0] + red[1] + red[2] + red[3];
    float mean = tot * (1.0f / C);

    float d0 = v0 - mean, d1 = v1 - mean, d2 = v2 - mean;
    float q = d0 * d0 + d1 * d1 + d2 * d2;
    __syncthreads();
    for (int o = 16; o > 0; o >>= 1) q += __shfl_down_sync(0xffffffffu, q, o);
    if ((tid & 31) == 0) red[tid >> 5] = q;
    __syncthreads();
    float var = (red[0] + red[1] + red[2] + red[3]) * (1.0f / C);
    float rstd = rsqrtf(var + 1e-5f);

    __half* yr = y + (size_t)t * C;
    yr[tid]       = __float2half(d0 * rstd * w[tid]       + b[tid]);
    yr[tid + 128] = __float2half(d1 * rstd * w[tid + 128] + b[tid + 128]);
    yr[tid + 256] = __float2half(d2 * rstd * w[tid + 256] + b[tid + 256]);
}

// ---------------- fp16 tensor-core GEMM, BK=64 3-stage, 4 warps --------------
// out[M,N] = A[M,K] @ W[N,K]^T ; 128x128 tile, 4 warps (2x2), 64x64 each.
// EPI 0: plain -> half
// EPI 1: +bias +res(half) -> half (row-major)
// EPI 2: +bias +GELU -> half
// EPI 3: +bias +res(half) -> f32 written TRANSPOSED as BCHW into d_out
#define ROWSTR 72
#define HST (128*ROWSTR)              // halves per stage per matrix (9216)
#define NSTAGE 3
#define TSTG_STRIDE 133
#define GEMM_SMEM (2*NSTAGE*HST*2)    // 110592 B  (2 CTAs = 216 KB <= 228 KB)
#define GT 128                        // threads per CTA

template<int EPI>
__global__ void __launch_bounds__(GT, 2)
hgemm_kernel(const __half* __restrict__ A, const __half* __restrict__ W,
             const float* __restrict__ bias, const __half* __restrict__ res,
             void* __restrict__ outv, int M, int N, int K)
{
    extern __shared__ __half smh[];
    __half* As = smh;                  // [NSTAGE][128][72]
    __half* Bs = smh + NSTAGE * HST;   // [NSTAGE][128][72]

    int tid = threadIdx.x;
    int lane = tid & 31, warp = tid >> 5;      // 4 warps
    int warpM = (warp >> 1) * 64;              // 0,64
    int warpN = (warp & 1) * 64;               // 0,64
    int gid = lane >> 2, tig = lane & 3;

    const __half* Abase = A + (size_t)(blockIdx.y * 128) * K;
    const __half* Wbase = W + (size_t)(blockIdx.x * 128) * K;
    int nk = K >> 6;   // 6 or 24

    uint32_t smA = (uint32_t)__cvta_generic_to_shared(As);
    uint32_t smB = (uint32_t)__cvta_generic_to_shared(Bs);
    uint32_t aAddr[4];
    #pragma unroll
    for (int mt = 0; mt < 4; mt++)
        aAddr[mt] = smA + (((warpM + mt * 16 + (lane & 15)) * ROWSTR + (lane >> 4) * 8) << 1);
    uint32_t bAddr[4];
    #pragma unroll
    for (int ntp = 0; ntp < 4; ntp++)
        bAddr[ntp] = smB + (((warpN + ntp * 16 + (lane & 7) + ((lane >> 4) << 3)) * ROWSTR
                             + (((lane >> 3) & 1) * 8)) << 1);

    auto issue = [&](int kt) {
        int st = kt % NSTAGE;
        #pragma unroll
        for (int i = 0; i < 8; i++) {
            int chunk = i * GT + tid;
            int row = chunk >> 3, kc = chunk & 7;
            cpasync16(As + st * HST + row * ROWSTR + kc * 8,
                      Abase + (size_t)row * K + kt * 64 + kc * 8);
        }
        #pragma unroll
        for (int i = 0; i < 8; i++) {
            int chunk = i * GT + tid;
            int row = chunk >> 3, kc = chunk & 7;
            cpasync16(Bs + st * HST + row * ROWSTR + kc * 8,
                      Wbase + (size_t)row * K + kt * 64 + kc * 8);
        }
        asm volatile("cp.async.commit_group;");
    };

    issue(0); issue(1);

    float acc[4][8][4] = {};

    for (int kt = 0; kt < nk; kt++) {
        asm volatile("cp.async.wait_group 1;");
        __syncthreads();
        if (kt + 2 < nk) issue(kt + 2);

        uint32_t stoff = (uint32_t)((kt % NSTAGE) * HST * 2);

        #pragma unroll
        for (int ks = 0; ks < 4; ks++) {
            uint32_t af[4][4], bf[8][2];
            #pragma unroll
            for (int mt = 0; mt < 4; mt++)
                LDMATRIX_X4(af[mt][0], af[mt][1], af[mt][2], af[mt][3],
                            aAddr[mt] + stoff + ks * 32);
            #pragma unroll
            for (int ntp = 0; ntp < 4; ntp++)
                LDMATRIX_X4(bf[2 * ntp][0], bf[2 * ntp][1], bf[2 * ntp + 1][0], bf[2 * ntp + 1][1],
                            bAddr[ntp] + stoff + ks * 32);
            #pragma unroll
            for (int mt = 0; mt < 4; mt++)
                #pragma unroll
                for (int nt = 0; nt < 8; nt++)
                    MMA_F16_K16(acc[mt][nt], af[mt], bf[nt]);
        }
    }

    if (EPI == 3) {
        float* stg = (float*)smh;   // [128][TSTG_STRIDE]
        asm volatile("cp.async.wait_group 0;");
        __syncthreads();
        int m0 = blockIdx.y * 128, n0 = blockIdx.x * 128;
        #pragma unroll
        for (int mt = 0; mt < 4; mt++) {
            #pragma unroll
            for (int half = 0; half < 2; half++) {
                int ri = warpM + mt * 16 + gid + half * 8;
                #pragma unroll
                for (int nt = 0; nt < 8; nt++) {
                    int ci = warpN + nt * 8 + 2 * tig;
                    int col = n0 + ci;
                    size_t oi = (size_t)(m0 + ri) * N + col;
                    __half2 rh = *(const __half2*)(res + oi);
                    float2 rf = __half22float2(rh);
                    stg[ri * TSTG_STRIDE + ci]     = acc[mt][nt][half * 2]     + bias[col]     + rf.x;
                    stg[ri * TSTG_STRIDE + ci + 1] = acc[mt][nt][half * 2 + 1] + bias[col + 1] + rf.y;
                }
            }
        }
        __syncthreads();
        float* outp = (float*)outv;
        #pragma unroll
        for (int i = 0; i < 128; i++) {
            int idx = i * GT + tid;
            int c = idx >> 7, r = idx & 127;
            int t = m0 + r;
            int bb = t / HW;
            int hw = t - bb * HW;
            outp[(size_t)(bb * C + n0 + c) * HW + hw] = stg[r * TSTG_STRIDE + c];
        }
        return;
    }

    #pragma unroll
    for (int mt = 0; mt < 4; mt++) {
        #pragma unroll
        for (int half = 0; half < 2; half++) {
            int r = blockIdx.y * 128 + warpM + mt * 16 + gid + half * 8;
            #pragma unroll
            for (int nt = 0; nt < 8; nt++) {
                int cc = blockIdx.x * 128 + warpN + nt * 8 + 2 * tig;
                float v0 = acc[mt][nt][half * 2 + 0];
                float v1 = acc[mt][nt][half * 2 + 1];
                size_t oi = (size_t)r * N + cc;
                if (EPI == 1) {
                    __half2 rh = *(const __half2*)(res + oi);
                    float2 rf = __half22float2(rh);
                    v0 += bias[cc]     + rf.x;
                    v1 += bias[cc + 1] + rf.y;
                } else if (EPI == 2) {
                    v0 += bias[cc];
                    v1 += bias[cc + 1];
                    v0 = 0.5f * v0 * (1.0f + erff(v0 * 0.70710678118654752f));
                    v1 = 0.5f * v1 * (1.0f + erff(v1 * 0.70710678118654752f));
                }
                *(__half2*)((__half*)outv + oi) = __floats2half2_rn(v0, v1);
            }
        }
    }
}

// ---------------- fp16 tensor-core windowed attention ------------------------
// Simplified softmax (no max-subtraction; scores O(1)). Row-sum lane reduction
// deferred to the end: per-thread partials in the chunk loop, 2 shuffles total.
#define AQ_STR 40
#define AVT_STR 232
#define A_SM_HALVES (2*224*AQ_STR + 32*AVT_STR)
#define A_SMEM_BYTES (A_SM_HALVES*2)              // 50688 B

__global__ void __launch_bounds__(224, 2)
attn_mma_kernel(const __half* __restrict__ qkv, __half* __restrict__ outp)
{
    extern __shared__ __half smh[];
    __half* Qs = smh;                     // [224][40]
    __half* Ks = smh + 224 * AQ_STR;      // [224][40]
    __half* VT = smh + 2 * 224 * AQ_STR;  // [32][232]

    int blk = blockIdx.x;
    int win = blk / HEADS;
    int head = blk - win * HEADS;
    int b = win / WIN_PER_B;
    int wr = win - b * WIN_PER_B;
    int h0 = (wr / NWIN_SIDE) * WS, w0 = (wr % NWIN_SIDE) * WS;

    int tid = threadIdx.x;
    int lane = tid & 31, warp = tid >> 5;
    int gid = lane >> 2, tig = lane & 3;
    const float scale = 0.17677669529663687f;

    {
        int r = tid;
        if (r < NTOKW) {
            int tok = b * HW + (h0 + r / WS) * WW + (w0 + r % WS);
            const uint4* q4 = (const uint4*)(qkv + (size_t)tok * QKV_DIM + head * DHEAD);
            const uint4* k4 = (const uint4*)(qkv + (size_t)tok * QKV_DIM + C + head * DHEAD);
            const uint4* v4 = (const uint4*)(qkv + (size_t)tok * QKV_DIM + 2 * C + head * DHEAD);
            #pragma unroll
            for (int i = 0; i < 4; i++) {
                uint4 qa = q4[i], ka = k4[i], va = v4[i];
                const __half2* qh = (const __half2*)&qa;
                const __half2* vh = (const __half2*)&va;
                #pragma unroll
                for (int j = 0; j < 4; j++) {
                    float2 f = __half22float2(qh[j]);
                    *(__half2*)(Qs + r * AQ_STR + i * 8 + 2 * j) =
                        __floats2half2_rn(f.x * scale, f.y * scale);
                }
                *(uint4*)(Ks + r * AQ_STR + i * 8) = ka;
                #pragma unroll
                for (int j = 0; j < 4; j++) {
                    int e = i * 8 + 2 * j;
                    VT[e * AVT_STR + r]       = __low2half(vh[j]);
                    VT[(e + 1) * AVT_STR + r] = __high2half(vh[j]);
                }
            }
        } else {
            uint4 z = {0, 0, 0, 0};
            #pragma unroll
            for (int i = 0; i < 4; i++) {
                *(uint4*)(Qs + r * AQ_STR + i * 8) = z;
                *(uint4*)(Ks + r * AQ_STR + i * 8) = z;
            }
            #pragma unroll
            for (int e = 0; e < DHEAD; e++) VT[e * AVT_STR + r] = __float2half(0.f);
        }
    }
    __syncthreads();

    float lS[2][2] = {};     // per-thread partial row sums (reduced at the end)
    float O[2][4][4] = {};

    #pragma unroll 1
    for (int ch = 0; ch < 4; ch++) {
        float S[2][7][4] = {};
        #pragma unroll
        for (int ks = 0; ks < 2; ks++) {
            uint32_t af[2][4];
            #pragma unroll
            for (int mt = 0; mt < 2; mt++) {
                int r = warp * 32 + mt * 16 + gid;
                af[mt][0] = *(const uint32_t*)(Qs + r * AQ_STR + ks * 16 + 2 * tig);
                af[mt][1] = *(const uint32_t*)(Qs + (r + 8) * AQ_STR + ks * 16 + 2 * tig);
                af[mt][2] = *(const uint32_t*)(Qs + r * AQ_STR + ks * 16 + 2 * tig + 8);
                af[mt][3] = *(const uint32_t*)(Qs + (r + 8) * AQ_STR + ks * 16 + 2 * tig + 8);
            }
            #pragma unroll
            for (int nt = 0; nt < 7; nt++) {
                int col = ch * 56 + nt * 8 + gid;
                uint32_t bf[2];
                bf[0] = *(const uint32_t*)(Ks + col * AQ_STR + ks * 16 + 2 * tig);
                bf[1] = *(const uint32_t*)(Ks + col * AQ_STR + ks * 16 + 2 * tig + 8);
                #pragma unroll
                for (int mt = 0; mt < 2; mt++)
                    MMA_F16_K16(S[mt][nt], af[mt], bf);
            }
        }
        if (ch == 3) {
            #pragma unroll
            for (int nt = 0; nt < 7; nt++) {
                int col0 = 168 + nt * 8 + 2 * tig;
                if (col0 >= NTOKW) {
                    #pragma unroll
                    for (int u = 0; u < 4; u++) { S[0][nt][u] = -1e30f; S[1][nt][u] = -1e30f; }
                }
            }
        }
        // exp + per-thread partial row-sum (no shuffles here)
        #pragma unroll
        for (int mt = 0; mt < 2; mt++) {
            #pragma unroll
            for (int hf = 0; hf < 2; hf++) {
                float rs = 0.f;
                #pragma unroll
                for (int nt = 0; nt < 7; nt++) {
                    float p0 = __expf(S[mt][nt][hf * 2]);
                    float p1 = __expf(S[mt][nt][hf * 2 + 1]);
                    S[mt][nt][hf * 2]     = p0;
                    S[mt][nt][hf * 2 + 1] = p1;
                    rs += p0 + p1;
                }
                lS[mt][hf] += rs;
            }
        }
        #pragma unroll
        for (int pj = 0; pj < 3; pj++) {
            uint32_t a[2][4];
            #pragma unroll
            for (int mt = 0; mt < 2; mt++) {
                a[mt][0] = pack_h2(S[mt][2 * pj][0],     S[mt][2 * pj][1]);
                a[mt][1] = pack_h2(S[mt][2 * pj][2],     S[mt][2 * pj][3]);
                a[mt][2] = pack_h2(S[mt][2 * pj + 1][0], S[mt][2 * pj + 1][1]);
                a[mt][3] = pack_h2(S[mt][2 * pj + 1][2], S[mt][2 * pj + 1][3]);
            }
            int key = ch * 56 + pj * 16;
            #pragma unroll
            for (int nv = 0; nv < 4; nv++) {
                uint32_t bf[2];
                bf[0] = *(const uint32_t*)(VT + (nv * 8 + gid) * AVT_STR + key + 2 * tig);
                bf[1] = *(const uint32_t*)(VT + (nv * 8 + gid) * AVT_STR + key + 2 * tig + 8);
                #pragma unroll
                for (int mt = 0; mt < 2; mt++)
                    MMA_F16_K16(O[mt][nv], a[mt], bf);
            }
        }
        {
            uint32_t a[2][2];
            #pragma unroll
            for (int mt = 0; mt < 2; mt++) {
                a[mt][0] = pack_h2(S[mt][6][0], S[mt][6][1]);
                a[mt][1] = pack_h2(S[mt][6][2], S[mt][6][3]);
            }
            int key = ch * 56 + 48;
            #pragma unroll
            for (int nv = 0; nv < 4; nv++) {
                uint32_t b0 = *(const uint32_t*)(VT + (nv * 8 + gid) * AVT_STR + key + 2 * tig);
                #pragma unroll
                for (int mt = 0; mt < 2; mt++)
                    MMA_F16_K8(O[mt][nv], a[mt], b0);
            }
        }
    }

    // final lane-group reduction of row sums (once, not per chunk)
    #pragma unroll
    for (int mt = 0; mt < 2; mt++)
        #pragma unroll
        for (int hf = 0; hf < 2; hf++) {
            lS[mt][hf] += __shfl_xor_sync(0xffffffffu, lS[mt][hf], 1);
            lS[mt][hf] += __shfl_xor_sync(0xffffffffu, lS[mt][hf], 2);
        }

    #pragma unroll
    for (int mt = 0; mt < 2; mt++) {
        #pragma unroll
        for (int hf = 0; hf < 2; hf++) {
            int r = warp * 32 + mt * 16 + gid + hf * 8;
            if (r < NTOKW) {
                int tok = b * HW + (h0 + r / WS) * WW + (w0 + r % WS);
                float inv = 1.f / lS[mt][hf];
                __half* op = outp + (size_t)tok * C + head * DHEAD;
                #pragma unroll
                for (int nv = 0; nv < 4; nv++) {
                    int cb2 = nv * 8 + 2 * tig;
                    *(__half2*)(op + cb2) =
                        __floats2half2_rn(O[mt][nv][hf * 2] * inv, O[mt][nv][hf * 2 + 1] * inv);
                }
            }
        }
    }
}

// ---------------- launcher ---------------------------------------------------
extern "C" void kernel_launch(void* const* d_in, const int* in_sizes, int n_in,
                              void* d_out, int out_size)
{
    const float* x      = (const float*)d_in[0];
    const float* conv_w = (const float*)d_in[1];
    const float* conv_b = (const float*)d_in[2];
    const float* ln1_w  = (const float*)d_in[3];
    const float* ln1_b  = (const float*)d_in[4];
    const float* qkv_w  = (const float*)d_in[5];
    const float* proj_w = (const float*)d_in[6];
    const float* proj_b = (const float*)d_in[7];
    const float* ln2_w  = (const float*)d_in[8];
    const float* ln2_b  = (const float*)d_in[9];
    const float* fc1_w  = (const float*)d_in[10];
    const float* fc1_b  = (const float*)d_in[11];
    const float* fc2_w  = (const float*)d_in[12];
    const float* fc2_b  = (const float*)d_in[13];
    float* out = (float*)d_out;

    __half *p_x1, *p_x2, *p_xn, *p_qkv, *p_attn, *p_h, *p_wq, *p_wp, *p_w1, *p_w2;
    cudaGetSymbolAddress((void**)&p_x1, g_x1);
    cudaGetSymbolAddress((void**)&p_x2, g_x2);
    cudaGetSymbolAddress((void**)&p_xn, g_xn);
    cudaGetSymbolAddress((void**)&p_qkv, g_qkv);
    cudaGetSymbolAddress((void**)&p_attn, g_attn);
    cudaGetSymbolAddress((void**)&p_h, g_h);
    cudaGetSymbolAddress((void**)&p_wq, g_wq);
    cudaGetSymbolAddress((void**)&p_wp, g_wp);
    cudaGetSymbolAddress((void**)&p_w1, g_w1);
    cudaGetSymbolAddress((void**)&p_w2, g_w2);

    cudaFuncSetAttribute(hgemm_kernel<0>, cudaFuncAttributeMaxDynamicSharedMemorySize, GEMM_SMEM);
    cudaFuncSetAttribute(hgemm_kernel<1>, cudaFuncAttributeMaxDynamicSharedMemorySize, GEMM_SMEM);
    cudaFuncSetAttribute(hgemm_kernel<2>, cudaFuncAttributeMaxDynamicSharedMemorySize, GEMM_SMEM);
    cudaFuncSetAttribute(hgemm_kernel<3>, cudaFuncAttributeMaxDynamicSharedMemorySize, GEMM_SMEM);
    cudaFuncSetAttribute(attn_mma_kernel, cudaFuncAttributeMaxDynamicSharedMemorySize, A_SMEM_BYTES);

    // 0. convert weights to half
    cvt_weights_kernel<<<(SQ + SP + S1 + S2 + 255) / 256, 256>>>(
        qkv_w, proj_w, fc1_w, fc2_w, p_wq, p_wp, p_w1, p_w2);

    // 1. depthwise conv + bias + residual -> BHWC half
    conv_pe_kernel<<<dim3(C / 32, HH, BATCH), 256>>>(x, conv_w, conv_b, p_x1);

    // 2. LN1 -> half
    ln_kernel<<<NTOK, 128>>>(p_x1, ln1_w, ln1_b, p_xn);

    // 3. QKV gemm
    hgemm_kernel<0><<<dim3(QKV_DIM / 128, NTOK / 128), GT, GEMM_SMEM>>>(
        p_xn, p_wq, nullptr, nullptr, p_qkv, NTOK, QKV_DIM, C);

    // 4. windowed attention
    attn_mma_kernel<<<NWIN * HEADS, 224, A_SMEM_BYTES>>>(p_qkv, p_attn);

    // 5. proj gemm + bias + residual(x1) -> half
    hgemm_kernel<1><<<dim3(C / 128, NTOK / 128), GT, GEMM_SMEM>>>(
        p_attn, p_wp, proj_b, p_x1, p_x2, NTOK, C, C);

    // 6. LN2 -> half
    ln_kernel<<<NTOK, 128>>>(p_x2, ln2_w, ln2_b, p_xn);

    // 7. fc1 gemm + bias + GELU -> half
    hgemm_kernel<2><<<dim3(MLP_HID / 128, NTOK / 128), GT, GEMM_SMEM>>>(
        p_xn, p_w1, fc1_b, nullptr, p_h, NTOK, MLP_HID, C);

    // 8. fc2 gemm + bias + residual(x2) -> fp32 BCHW directly into d_out
    hgemm_kernel<3><<<dim3(C / 128, NTOK / 128), GT, GEMM_SMEM>>>(
        p_h, p_w2, fc2_b, p_x2, out, NTOK, C, MLP_HID);
}

// round 17
// speedup vs baseline: 1.0015x; 1.0015x over previous
#include <cuda_runtime.h>
#include <cuda_fp16.h>
#include <math.h>
#include <stdint.h>

// Problem constants
#define BATCH 16
#define C 384
#define HH 56
#define WW 56
#define HW (HH*WW)            // 3136
#define NTOK (BATCH*HW)       // 50176
#define HEADS 12
#define DHEAD 32
#define WS 14
#define NWIN_SIDE 4
#define WIN_PER_B 16
#define NWIN (BATCH*WIN_PER_B) // 256
#define NTOKW (WS*WS)          // 196
#define MLP_HID (4*C)          // 1536
#define QKV_DIM (3*C)          // 1152

// ---------------- scratch buffers -------------------------------------------
__device__ __half g_x1[(size_t)NTOK * C];        // residual stream (half)
__device__ __half g_x2[(size_t)NTOK * C];
__device__ __half g_xn[(size_t)NTOK * C];        // LN out (half)
__device__ __half g_qkv[(size_t)NTOK * QKV_DIM];
__device__ __half g_attn[(size_t)NTOK * C];
__device__ __half g_h[(size_t)NTOK * MLP_HID];
// half weight copies
__device__ __half g_wq[(size_t)QKV_DIM * C];
__device__ __half g_wp[(size_t)C * C];
__device__ __half g_w1[(size_t)MLP_HID * C];
__device__ __half g_w2[(size_t)C * MLP_HID];

__device__ __forceinline__ uint32_t pack_h2(float a, float b) {
    __half2 h = __floats2half2_rn(a, b);
    return *reinterpret_cast<uint32_t*>(&h);
}

#define MMA_F16_K16(d, a, b)                                           \
    asm volatile(                                                      \
        "mma.sync.aligned.m16n8k16.row.col.f32.f16.f16.f32 "           \
        "{%0,%1,%2,%3},{%4,%5,%6,%7},{%8,%9},{%0,%1,%2,%3};\n"         \
        : "+f"(d[0]), "+f"(d[1]), "+f"(d[2]), "+f"(d[3])               \
        : "r"(a[0]), "r"(a[1]), "r"(a[2]), "r"(a[3]), "r"(b[0]), "r"(b[1]))

#define MMA_F16_K8(d, a, b0)                                           \
    asm volatile(                                                      \
        "mma.sync.aligned.m16n8k8.row.col.f32.f16.f16.f32 "            \
        "{%0,%1,%2,%3},{%4,%5},{%6},{%0,%1,%2,%3};\n"                  \
        : "+f"(d[0]), "+f"(d[1]), "+f"(d[2]), "+f"(d[3])               \
        : "r"(a[0]), "r"(a[1]), "r"(b0))

#define LDMATRIX_X4(r0, r1, r2, r3, addr)                              \
    asm volatile("ldmatrix.sync.aligned.m8n8.x4.shared.b16 "           \
                 "{%0,%1,%2,%3}, [%4];"                                \
                 : "=r"(r0), "=r"(r1), "=r"(r2), "=r"(r3) : "r"(addr))

__device__ __forceinline__ void cpasync16(void* smem_dst, const void* gsrc) {
    uint32_t s = (uint32_t)__cvta_generic_to_shared(smem_dst);
    asm volatile("cp.async.cg.shared.global [%0], [%1], 16;" :: "r"(s), "l"(gsrc));
}

// ---------------- weight conversion fp32 -> fp16 -----------------------------
#define SQ (QKV_DIM*C)
#define SP (C*C)
#define S1 (MLP_HID*C)
#define S2 (C*MLP_HID)
__global__ void cvt_weights_kernel(const float* __restrict__ wq, const float* __restrict__ wp,
                                   const float* __restrict__ w1, const float* __restrict__ w2,
                                   __half* oq, __half* op_, __half* o1, __half* o2)
{
    int i = blockIdx.x * 256 + threadIdx.x;
    if (i < SQ) oq[i] = __float2half(wq[i]);
    else if (i < SQ + SP) op_[i - SQ] = __float2half(wp[i - SQ]);
    else if (i < SQ + SP + S1) o1[i - SQ - SP] = __float2half(w1[i - SQ - SP]);
    else if (i < SQ + SP + S1 + S2) o2[i - SQ - SP - S1] = __float2half(w2[i - SQ - SP - S1]);
}

// ---------------- depthwise conv + bias + residual, NCHW -> BHWC (half out) --
__global__ void conv_pe_kernel(const float* __restrict__ x,
                               const float* __restrict__ cw,
                               const float* __restrict__ cb,
                               __half* __restrict__ out)
{
    __shared__ float sx[3][58][33];
    int c0 = blockIdx.x * 32;
    int h  = blockIdx.y;
    int b  = blockIdx.z;
    int tid = threadIdx.x;

    for (int idx = tid; idx < 32 * 3 * 58; idx += 256) {
        int wq = idx % 58;
        int t  = idx / 58;
        int hh = t % 3;
        int c  = t / 3;
        int gh = h + hh - 1, gw = wq - 1;
        float v = 0.f;
        if (gh >= 0 && gh < HH && gw >= 0 && gw < WW)
            v = x[(size_t)(b * C + c0 + c) * HW + gh * WW + gw];
        sx[hh][wq][c] = v;
    }
    __syncthreads();

    for (int o = tid; o < 16 * WW; o += 256) {
        int cp = (o & 15) * 2, w = o >> 4;
        float s0 = cb[c0 + cp]     + sx[1][w + 1][cp];
        float s1 = cb[c0 + cp + 1] + sx[1][w + 1][cp + 1];
        const float* wt0 = cw + (size_t)(c0 + cp) * 9;
        const float* wt1 = wt0 + 9;
        #pragma unroll
        for (int dy = 0; dy < 3; dy++)
            #pragma unroll
            for (int dx = 0; dx < 3; dx++) {
                s0 += sx[dy][w + dx][cp]     * wt0[dy * 3 + dx];
                s1 += sx[dy][w + dx][cp + 1] * wt1[dy * 3 + dx];
            }
        *(__half2*)(out + (size_t)(b * HW + h * WW + w) * C + c0 + cp) =
            __floats2half2_rn(s0, s1);
    }
}

// ---------------- layer norm: warp per token, shuffle-only -------------------
// 256 threads = 8 warps = 8 tokens per block; each lane owns 6 half2 (12 ch).
__global__ void __launch_bounds__(256)
ln_kernel(const __half* __restrict__ x,
          const float* __restrict__ w,
          const float* __restrict__ b,
          __half* __restrict__ y)
{
    int warp = threadIdx.x >> 5, lane = threadIdx.x & 31;
    size_t tok = (size_t)blockIdx.x * 8 + warp;
    const __half2* xr = (const __half2*)(x + tok * C);

    float2 v[6];
    float s = 0.f;
    #pragma unroll
    for (int j = 0; j < 6; j++) {
        v[j] = __half22float2(xr[lane + 32 * j]);
        s += v[j].x + v[j].y;
    }
    #pragma unroll
    for (int o = 16; o > 0; o >>= 1) s += __shfl_xor_sync(0xffffffffu, s, o);
    float mean = s * (1.0f / C);

    float q = 0.f;
    #pragma unroll
    for (int j = 0; j < 6; j++) {
        float d0 = v[j].x - mean, d1 = v[j].y - mean;
        q += d0 * d0 + d1 * d1;
    }
    #pragma unroll
    for (int o = 16; o > 0; o >>= 1) q += __shfl_xor_sync(0xffffffffu, q, o);
    float rstd = rsqrtf(q * (1.0f / C) + 1e-5f);

    __half2* yr = (__half2*)(y + tok * C);
    #pragma unroll
    for (int j = 0; j < 6; j++) {
        int c = (lane + 32 * j) * 2;
        float o0 = (v[j].x - mean) * rstd * w[c]     + b[c];
        float o1 = (v[j].y - mean) * rstd * w[c + 1] + b[c + 1];
        yr[lane + 32 * j] = __floats2half2_rn(o0, o1);
    }
}

// ---------------- fp16 tensor-core GEMM, BK=64 3-stage, 8 warps --------------
// 128x128 tile, 8 warps (4x2), 32x64 each; fragment double-buffering across
// the 4 k16 sub-steps (discriminates latency-bound vs rate-bound tensor pipe).
// EPI 0: plain -> half
// EPI 1: +bias +res(half) -> half (row-major)
// EPI 2: +bias +GELU -> half
// EPI 3: +bias +res(half) -> f32 written TRANSPOSED as BCHW into d_out
#define ROWSTR 72
#define HST (128*ROWSTR)              // halves per stage per matrix (9216)
#define NSTAGE 3
#define TSTG_STRIDE 133
#define GEMM_SMEM (2*NSTAGE*HST*2)    // 110592 B  (2 CTAs = 216 KB <= 228 KB)
#define GT 256

template<int EPI>
__global__ void __launch_bounds__(GT, 2)
hgemm_kernel(const __half* __restrict__ A, const __half* __restrict__ W,
             const float* __restrict__ bias, const __half* __restrict__ res,
             void* __restrict__ outv, int M, int N, int K)
{
    extern __shared__ __half smh[];
    __half* As = smh;                  // [NSTAGE][128][72]
    __half* Bs = smh + NSTAGE * HST;   // [NSTAGE][128][72]

    int tid = threadIdx.x;
    int lane = tid & 31, warp = tid >> 5;      // 8 warps
    int warpM = (warp >> 1) * 32;              // 0,32,64,96
    int warpN = (warp & 1) * 64;               // 0,64
    int gid = lane >> 2, tig = lane & 3;

    const __half* Abase = A + (size_t)(blockIdx.y * 128) * K;
    const __half* Wbase = W + (size_t)(blockIdx.x * 128) * K;
    int nk = K >> 6;   // 6 or 24

    uint32_t smA = (uint32_t)__cvta_generic_to_shared(As);
    uint32_t smB = (uint32_t)__cvta_generic_to_shared(Bs);
    uint32_t aAddr[2];
    #pragma unroll
    for (int mt = 0; mt < 2; mt++)
        aAddr[mt] = smA + (((warpM + mt * 16 + (lane & 15)) * ROWSTR + (lane >> 4) * 8) << 1);
    uint32_t bAddr[4];
    #pragma unroll
    for (int ntp = 0; ntp < 4; ntp++)
        bAddr[ntp] = smB + (((warpN + ntp * 16 + (lane & 7) + ((lane >> 4) << 3)) * ROWSTR
                             + (((lane >> 3) & 1) * 8)) << 1);

    auto issue = [&](int kt) {
        int st = kt % NSTAGE;
        // 128 rows x 64 halves = 1024 chunks per matrix -> 4/thread
        #pragma unroll
        for (int i = 0; i < 4; i++) {
            int chunk = i * GT + tid;
            int row = chunk >> 3, kc = chunk & 7;
            cpasync16(As + st * HST + row * ROWSTR + kc * 8,
                      Abase + (size_t)row * K + kt * 64 + kc * 8);
        }
        #pragma unroll
        for (int i = 0; i < 4; i++) {
            int chunk = i * GT + tid;
            int row = chunk >> 3, kc = chunk & 7;
            cpasync16(Bs + st * HST + row * ROWSTR + kc * 8,
                      Wbase + (size_t)row * K + kt * 64 + kc * 8);
        }
        asm volatile("cp.async.commit_group;");
    };

    issue(0); issue(1);

    float acc[2][8][4] = {};
    uint32_t af[2][2][4], bf[2][8][2];   // double-buffered fragments

    auto load_frags = [&](int buf, uint32_t off) {
        #pragma unroll
        for (int mt = 0; mt < 2; mt++)
            LDMATRIX_X4(af[buf][mt][0], af[buf][mt][1], af[buf][mt][2], af[buf][mt][3],
                        aAddr[mt] + off);
        #pragma unroll
        for (int ntp = 0; ntp < 4; ntp++)
            LDMATRIX_X4(bf[buf][2 * ntp][0], bf[buf][2 * ntp][1],
                        bf[buf][2 * ntp + 1][0], bf[buf][2 * ntp + 1][1],
                        bAddr[ntp] + off);
    };

    for (int kt = 0; kt < nk; kt++) {
        asm volatile("cp.async.wait_group 1;");
        __syncthreads();
        if (kt + 2 < nk) issue(kt + 2);

        uint32_t stoff = (uint32_t)((kt % NSTAGE) * HST * 2);

        load_frags(0, stoff);
        #pragma unroll
        for (int ks = 0; ks < 4; ks++) {
            int cur = ks & 1;
            if (ks < 3) load_frags(cur ^ 1, stoff + (ks + 1) * 32);
            #pragma unroll
            for (int mt = 0; mt < 2; mt++)
                #pragma unroll
                for (int nt = 0; nt < 8; nt++)
                    MMA_F16_K16(acc[mt][nt], af[cur][mt], bf[cur][nt]);
        }
    }

    if (EPI == 3) {
        float* stg = (float*)smh;   // [128][TSTG_STRIDE]
        asm volatile("cp.async.wait_group 0;");
        __syncthreads();
        int m0 = blockIdx.y * 128, n0 = blockIdx.x * 128;
        #pragma unroll
        for (int mt = 0; mt < 2; mt++) {
            #pragma unroll
            for (int half = 0; half < 2; half++) {
                int ri = warpM + mt * 16 + gid + half * 8;
                #pragma unroll
                for (int nt = 0; nt < 8; nt++) {
                    int ci = warpN + nt * 8 + 2 * tig;
                    int col = n0 + ci;
                    size_t oi = (size_t)(m0 + ri) * N + col;
                    __half2 rh = *(const __half2*)(res + oi);
                    float2 rf = __half22float2(rh);
                    stg[ri * TSTG_STRIDE + ci]     = acc[mt][nt][half * 2]     + bias[col]     + rf.x;
                    stg[ri * TSTG_STRIDE + ci + 1] = acc[mt][nt][half * 2 + 1] + bias[col + 1] + rf.y;
                }
            }
        }
        __syncthreads();
        float* outp = (float*)outv;
        #pragma unroll
        for (int i = 0; i < 64; i++) {
            int idx = i * GT + tid;
            int c = idx >> 7, r = idx & 127;
            int t = m0 + r;
            int bb = t / HW;
            int hw = t - bb * HW;
            outp[(size_t)(bb * C + n0 + c) * HW + hw] = stg[r * TSTG_STRIDE + c];
        }
        return;
    }

    #pragma unroll
    for (int mt = 0; mt < 2; mt++) {
        #pragma unroll
        for (int half = 0; half < 2; half++) {
            int r = blockIdx.y * 128 + warpM + mt * 16 + gid + half * 8;
            #pragma unroll
            for (int nt = 0; nt < 8; nt++) {
                int cc = blockIdx.x * 128 + warpN + nt * 8 + 2 * tig;
                float v0 = acc[mt][nt][half * 2 + 0];
                float v1 = acc[mt][nt][half * 2 + 1];
                size_t oi = (size_t)r * N + cc;
                if (EPI == 1) {
                    __half2 rh = *(const __half2*)(res + oi);
                    float2 rf = __half22float2(rh);
                    v0 += bias[cc]     + rf.x;
                    v1 += bias[cc + 1] + rf.y;
                } else if (EPI == 2) {
                    v0 += bias[cc];
                    v1 += bias[cc + 1];
                    v0 = 0.5f * v0 * (1.0f + erff(v0 * 0.70710678118654752f));
                    v1 = 0.5f * v1 * (1.0f + erff(v1 * 0.70710678118654752f));
                }
                *(__half2*)((__half*)outv + oi) = __floats2half2_rn(v0, v1);
            }
        }
    }
}

// ---------------- fp16 tensor-core windowed attention ------------------------
#define AQ_STR 40
#define AVT_STR 232
#define A_SM_HALVES (2*224*AQ_STR + 32*AVT_STR)
#define A_SMEM_BYTES (A_SM_HALVES*2)              // 50688 B

__global__ void __launch_bounds__(224, 2)
attn_mma_kernel(const __half* __restrict__ qkv, __half* __restrict__ outp)
{
    extern __shared__ __half smh[];
    __half* Qs = smh;                     // [224][40]
    __half* Ks = smh + 224 * AQ_STR;      // [224][40]
    __half* VT = smh + 2 * 224 * AQ_STR;  // [32][232]

    int blk = blockIdx.x;
    int win = blk / HEADS;
    int head = blk - win * HEADS;
    int b = win / WIN_PER_B;
    int wr = win - b * WIN_PER_B;
    int h0 = (wr / NWIN_SIDE) * WS, w0 = (wr % NWIN_SIDE) * WS;

    int tid = threadIdx.x;
    int lane = tid & 31, warp = tid >> 5;
    int gid = lane >> 2, tig = lane & 3;
    const float scale = 0.17677669529663687f;

    {
        int r = tid;
        if (r < NTOKW) {
            int tok = b * HW + (h0 + r / WS) * WW + (w0 + r % WS);
            const uint4* q4 = (const uint4*)(qkv + (size_t)tok * QKV_DIM + head * DHEAD);
            const uint4* k4 = (const uint4*)(qkv + (size_t)tok * QKV_DIM + C + head * DHEAD);
            const uint4* v4 = (const uint4*)(qkv + (size_t)tok * QKV_DIM + 2 * C + head * DHEAD);
            #pragma unroll
            for (int i = 0; i < 4; i++) {
                uint4 qa = q4[i], ka = k4[i], va = v4[i];
                const __half2* qh = (const __half2*)&qa;
                const __half2* vh = (const __half2*)&va;
                #pragma unroll
                for (int j = 0; j < 4; j++) {
                    float2 f = __half22float2(qh[j]);
                    *(__half2*)(Qs + r * AQ_STR + i * 8 + 2 * j) =
                        __floats2half2_rn(f.x * scale, f.y * scale);
                }
                *(uint4*)(Ks + r * AQ_STR + i * 8) = ka;
                #pragma unroll
                for (int j = 0; j < 4; j++) {
                    int e = i * 8 + 2 * j;
                    VT[e * AVT_STR + r]       = __low2half(vh[j]);
                    VT[(e + 1) * AVT_STR + r] = __high2half(vh[j]);
                }
            }
        } else {
            uint4 z = {0, 0, 0, 0};
            #pragma unroll
            for (int i = 0; i < 4; i++) {
                *(uint4*)(Qs + r * AQ_STR + i * 8) = z;
                *(uint4*)(Ks + r * AQ_STR + i * 8) = z;
            }
            #pragma unroll
            for (int e = 0; e < DHEAD; e++) VT[e * AVT_STR + r] = __float2half(0.f);
        }
    }
    __syncthreads();

    float lS[2][2] = {};
    float O[2][4][4] = {};

    #pragma unroll 1
    for (int ch = 0; ch < 4; ch++) {
        float S[2][7][4] = {};
        #pragma unroll
        for (int ks = 0; ks < 2; ks++) {
            uint32_t af[2][4];
            #pragma unroll
            for (int mt = 0; mt < 2; mt++) {
                int r = warp * 32 + mt * 16 + gid;
                af[mt][0] = *(const uint32_t*)(Qs + r * AQ_STR + ks * 16 + 2 * tig);
                af[mt][1] = *(const uint32_t*)(Qs + (r + 8) * AQ_STR + ks * 16 + 2 * tig);
                af[mt][2] = *(const uint32_t*)(Qs + r * AQ_STR + ks * 16 + 2 * tig + 8);
                af[mt][3] = *(const uint32_t*)(Qs + (r + 8) * AQ_STR + ks * 16 + 2 * tig + 8);
            }
            #pragma unroll
            for (int nt = 0; nt < 7; nt++) {
                int col = ch * 56 + nt * 8 + gid;
                uint32_t bf[2];
                bf[0] = *(const uint32_t*)(Ks + col * AQ_STR + ks * 16 + 2 * tig);
                bf[1] = *(const uint32_t*)(Ks + col * AQ_STR + ks * 16 + 2 * tig + 8);
                #pragma unroll
                for (int mt = 0; mt < 2; mt++)
                    MMA_F16_K16(S[mt][nt], af[mt], bf);
            }
        }
        if (ch == 3) {
            #pragma unroll
            for (int nt = 0; nt < 7; nt++) {
                int col0 = 168 + nt * 8 + 2 * tig;
                if (col0 >= NTOKW) {
                    #pragma unroll
                    for (int u = 0; u < 4; u++) { S[0][nt][u] = -1e30f; S[1][nt][u] = -1e30f; }
                }
            }
        }
        #pragma unroll
        for (int mt = 0; mt < 2; mt++) {
            #pragma unroll
            for (int hf = 0; hf < 2; hf++) {
                float rs = 0.f;
                #pragma unroll
                for (int nt = 0; nt < 7; nt++) {
                    float p0 = __expf(S[mt][nt][hf * 2]);
                    float p1 = __expf(S[mt][nt][hf * 2 + 1]);
                    S[mt][nt][hf * 2]     = p0;
                    S[mt][nt][hf * 2 + 1] = p1;
                    rs += p0 + p1;
                }
                lS[mt][hf] += rs;
            }
        }
        #pragma unroll
        for (int pj = 0; pj < 3; pj++) {
            uint32_t a[2][4];
            #pragma unroll
            for (int mt = 0; mt < 2; mt++) {
                a[mt][0] = pack_h2(S[mt][2 * pj][0],     S[mt][2 * pj][1]);
                a[mt][1] = pack_h2(S[mt][2 * pj][2],     S[mt][2 * pj][3]);
                a[mt][2] = pack_h2(S[mt][2 * pj + 1][0], S[mt][2 * pj + 1][1]);
                a[mt][3] = pack_h2(S[mt][2 * pj + 1][2], S[mt][2 * pj + 1][3]);
            }
            int key = ch * 56 + pj * 16;
            #pragma unroll
            for (int nv = 0; nv < 4; nv++) {
                uint32_t bf[2];
                bf[0] = *(const uint32_t*)(VT + (nv * 8 + gid) * AVT_STR + key + 2 * tig);
                bf[1] = *(const uint32_t*)(VT + (nv * 8 + gid) * AVT_STR + key + 2 * tig + 8);
                #pragma unroll
                for (int mt = 0; mt < 2; mt++)
                    MMA_F16_K16(O[mt][nv], a[mt], bf);
            }
        }
        {
            uint32_t a[2][2];
            #pragma unroll
            for (int mt = 0; mt < 2; mt++) {
                a[mt][0] = pack_h2(S[mt][6][0], S[mt][6][1]);
                a[mt][1] = pack_h2(S[mt][6][2], S[mt][6][3]);
            }
            int key = ch * 56 + 48;
            #pragma unroll
            for (int nv = 0; nv < 4; nv++) {
                uint32_t b0 = *(const uint32_t*)(VT + (nv * 8 + gid) * AVT_STR + key + 2 * tig);
                #pragma unroll
                for (int mt = 0; mt < 2; mt++)
                    MMA_F16_K8(O[mt][nv], a[mt], b0);
            }
        }
    }

    #pragma unroll
    for (int mt = 0; mt < 2; mt++)
        #pragma unroll
        for (int hf = 0; hf < 2; hf++) {
            lS[mt][hf] += __shfl_xor_sync(0xffffffffu, lS[mt][hf], 1);
            lS[mt][hf] += __shfl_xor_sync(0xffffffffu, lS[mt][hf], 2);
        }

    #pragma unroll
    for (int mt = 0; mt < 2; mt++) {
        #pragma unroll
        for (int hf = 0; hf < 2; hf++) {
            int r = warp * 32 + mt * 16 + gid + hf * 8;
            if (r < NTOKW) {
                int tok = b * HW + (h0 + r / WS) * WW + (w0 + r % WS);
                float inv = 1.f / lS[mt][hf];
                __half* op = outp + (size_t)tok * C + head * DHEAD;
                #pragma unroll
                for (int nv = 0; nv < 4; nv++) {
                    int cb2 = nv * 8 + 2 * tig;
                    *(__half2*)(op + cb2) =
                        __floats2half2_rn(O[mt][nv][hf * 2] * inv, O[mt][nv][hf * 2 + 1] * inv);
                }
            }
        }
    }
}

// ---------------- launcher ---------------------------------------------------
extern "C" void kernel_launch(void* const* d_in, const int* in_sizes, int n_in,
                              void* d_out, int out_size)
{
    const float* x      = (const float*)d_in[0];
    const float* conv_w = (const float*)d_in[1];
    const float* conv_b = (const float*)d_in[2];
    const float* ln1_w  = (const float*)d_in[3];
    const float* ln1_b  = (const float*)d_in[4];
    const float* qkv_w  = (const float*)d_in[5];
    const float* proj_w = (const float*)d_in[6];
    const float* proj_b = (const float*)d_in[7];
    const float* ln2_w  = (const float*)d_in[8];
    const float* ln2_b  = (const float*)d_in[9];
    const float* fc1_w  = (const float*)d_in[10];
    const float* fc1_b  = (const float*)d_in[11];
    const float* fc2_w  = (const float*)d_in[12];
    const float* fc2_b  = (const float*)d_in[13];
    float* out = (float*)d_out;

    __half *p_x1, *p_x2, *p_xn, *p_qkv, *p_attn, *p_h, *p_wq, *p_wp, *p_w1, *p_w2;
    cudaGetSymbolAddress((void**)&p_x1, g_x1);
    cudaGetSymbolAddress((void**)&p_x2, g_x2);
    cudaGetSymbolAddress((void**)&p_xn, g_xn);
    cudaGetSymbolAddress((void**)&p_qkv, g_qkv);
    cudaGetSymbolAddress((void**)&p_attn, g_attn);
    cudaGetSymbolAddress((void**)&p_h, g_h);
    cudaGetSymbolAddress((void**)&p_wq, g_wq);
    cudaGetSymbolAddress((void**)&p_wp, g_wp);
    cudaGetSymbolAddress((void**)&p_w1, g_w1);
    cudaGetSymbolAddress((void**)&p_w2, g_w2);

    cudaFuncSetAttribute(hgemm_kernel<0>, cudaFuncAttributeMaxDynamicSharedMemorySize, GEMM_SMEM);
    cudaFuncSetAttribute(hgemm_kernel<1>, cudaFuncAttributeMaxDynamicSharedMemorySize, GEMM_SMEM);
    cudaFuncSetAttribute(hgemm_kernel<2>, cudaFuncAttributeMaxDynamicSharedMemorySize, GEMM_SMEM);
    cudaFuncSetAttribute(hgemm_kernel<3>, cudaFuncAttributeMaxDynamicSharedMemorySize, GEMM_SMEM);
    cudaFuncSetAttribute(attn_mma_kernel, cudaFuncAttributeMaxDynamicSharedMemorySize, A_SMEM_BYTES);

    // 0. convert weights to half
    cvt_weights_kernel<<<(SQ + SP + S1 + S2 + 255) / 256, 256>>>(
        qkv_w, proj_w, fc1_w, fc2_w, p_wq, p_wp, p_w1, p_w2);

    // 1. depthwise conv + bias + residual -> BHWC half
    conv_pe_kernel<<<dim3(C / 32, HH, BATCH), 256>>>(x, conv_w, conv_b, p_x1);

    // 2. LN1 -> half (warp per token)
    ln_kernel<<<NTOK / 8, 256>>>(p_x1, ln1_w, ln1_b, p_xn);

    // 3. QKV gemm
    hgemm_kernel<0><<<dim3(QKV_DIM / 128, NTOK / 128), GT, GEMM_SMEM>>>(
        p_xn, p_wq, nullptr, nullptr, p_qkv, NTOK, QKV_DIM, C);

    // 4. windowed attention
    attn_mma_kernel<<<NWIN * HEADS, 224, A_SMEM_BYTES>>>(p_qkv, p_attn);

    // 5. proj gemm + bias + residual(x1) -> half
    hgemm_kernel<1><<<dim3(C / 128, NTOK / 128), GT, GEMM_SMEM>>>(
        p_attn, p_wp, proj_b, p_x1, p_x2, NTOK, C, C);

    // 6. LN2 -> half
    ln_kernel<<<NTOK / 8, 256>>>(p_x2, ln2_w, ln2_b, p_xn);

    // 7. fc1 gemm + bias + GELU -> half
    hgemm_kernel<2><<<dim3(MLP_HID / 128, NTOK / 128), GT, GEMM_SMEM>>>(
        p_xn, p_w1, fc1_b, nullptr, p_h, NTOK, MLP_HID, C);

    // 8. fc2 gemm + bias + residual(x2) -> fp32 BCHW directly into d_out
    hgemm_kernel<3><<<dim3(C / 128, NTOK / 128), GT, GEMM_SMEM>>>(
        p_h, p_w2, fc2_b, p_x2, out, NTOK, C, MLP_HID);
}